// round 1
// baseline (speedup 1.0000x reference)
#include <cuda_runtime.h>

#define L      512
#define NT     128
#define NSIG   4096
#define NTOT   (32*512*128)

// Scratch: __device__ globals (allocation inside kernel_launch is forbidden)
__device__ float g_omega[NSIG * 2];
__device__ int   g_swap[32];

__device__ __forceinline__ float warpsum(float v) {
#pragma unroll
    for (int o = 16; o; o >>= 1) v += __shfl_xor_sync(0xffffffffu, v, o);
    return v;
}

// In-place 512-pt complex FFT on shared arrays, 128 threads.
// inv=0: forward (e^{-i}), inv=1: inverse twiddles (e^{+i}), NO 1/N scaling.
__device__ void fft512(float* re, float* im, const float* Wr, const float* Wi,
                       int inv, int tid) {
    __syncthreads();
    // bit reversal (9-bit)
#pragma unroll
    for (int t = tid; t < L; t += NT) {
        int r = (int)(__brev((unsigned)t) >> 23);
        if (r > t) {
            float a = re[t], b = im[t];
            re[t] = re[r]; im[t] = im[r];
            re[r] = a;     im[r] = b;
        }
    }
    __syncthreads();
#pragma unroll
    for (int s = 1; s <= 9; s++) {
        int mh = 1 << (s - 1);
#pragma unroll
        for (int t = tid; t < 256; t += NT) {
            int p  = t & (mh - 1);
            int i1 = ((t >> (s - 1)) << s) + p;
            int i2 = i1 + mh;
            int q  = p << (9 - s);
            float wr = Wr[q];
            float wi = inv ? -Wi[q] : Wi[q];
            float br = re[i2], bi = im[i2];
            float tr = br * wr - bi * wi;
            float ti = br * wi + bi * wr;
            float ar = re[i1], ai = im[i1];
            re[i1] = ar + tr; im[i1] = ai + ti;
            re[i2] = ar - tr; im[i2] = ai - ti;
        }
        __syncthreads();
    }
}

// One CTA = one (b,d) signal. All spectra kept in UNSHIFTED fft order.
// shifted index j <-> unshifted k via k = j ^ 256 ; f_k = (k<256 ? k : k-512)/512
__global__ void __launch_bounds__(NT) vmd_main(const float* __restrict__ x,
                                               float* __restrict__ out) {
    __shared__ float Xr[L], Xi[L];
    __shared__ float U0r[L], U0i[L], U1r[L], U1i[L];
    __shared__ float Sr[L], Si[L];
    __shared__ float lam[L], xs[L];
    __shared__ float Wr[256], Wi[256];
    __shared__ float red[16];

    const int tid = threadIdx.x;
    const int sig = blockIdx.x;
    const int b = sig >> 7, d = sig & 127;
    const float* xp = x + (size_t)b * 65536 + d;

    // twiddle table W[q] = e^{-2*pi*i*q/512}
    for (int q = tid; q < 256; q += NT) {
        float sv, cv;
        sincosf(-6.283185307179586f * (float)q * (1.0f / 512.0f), &sv, &cv);
        Wr[q] = cv; Wi[q] = sv;
    }
    // load signal + init state
#pragma unroll
    for (int t = tid; t < L; t += NT) {
        float v = xp[(size_t)t * 128];
        xs[t] = v;
        Xr[t] = v;  Xi[t] = 0.0f;
        U0r[t] = 0.0f; U0i[t] = 0.0f;
        U1r[t] = 0.0f; U1i[t] = 0.0f;
        lam[t] = 0.0f;
    }
    fft512(Xr, Xi, Wr, Wi, 0, tid);   // X = fft(x) (unshifted order)

    float om0 = 0.0f, om1 = 0.0f;

    for (int it = 0; it < 50; it++) {
        // (a) S = Herm(U1) = fft(real(ifft(U1)))
#pragma unroll
        for (int t = tid; t < L; t += NT) {
            int m = (L - t) & (L - 1);
            Sr[t] = 0.5f * (U1r[t] + U1r[m]);
            Si[t] = 0.5f * (U1i[t] - U1i[m]);
        }
        __syncthreads();
        // (b) U0 = (X - S + lam_shift/2) / (1 + 2a(f-om0)^2)
#pragma unroll
        for (int t = tid; t < L; t += NT) {
            float fk = (float)((t < 256) ? t : t - 512) * (1.0f / 512.0f);
            float df = fk - om0;
            float invden = 1.0f / (1.0f + 1600.0f * df * df);
            U0r[t] = (Xr[t] - Sr[t] + 0.5f * lam[t ^ 256]) * invden;
            U0i[t] = (Xi[t] - Si[t]) * invden;
        }
        __syncthreads();
        // (c) S = Herm(U0); accumulate omega0 power sums over f>=0 (k=0..255)
        float n0 = 0.0f, d0 = 0.0f;
#pragma unroll
        for (int t = tid; t < L; t += NT) {
            int m = (L - t) & (L - 1);
            float hr = 0.5f * (U0r[t] + U0r[m]);
            float hi = 0.5f * (U0i[t] - U0i[m]);
            Sr[t] = hr; Si[t] = hi;
            if (t < 256) {
                float p = hr * hr + hi * hi;
                n0 += (float)t * (1.0f / 512.0f) * p;
                d0 += p;
            }
        }
        __syncthreads();
        // (d) U1 = (X - S + lam_shift/2) / (1 + 2a(f-om1)^2)
#pragma unroll
        for (int t = tid; t < L; t += NT) {
            float fk = (float)((t < 256) ? t : t - 512) * (1.0f / 512.0f);
            float df = fk - om1;
            float invden = 1.0f / (1.0f + 1600.0f * df * df);
            U1r[t] = (Xr[t] - Sr[t] + 0.5f * lam[t ^ 256]) * invden;
            U1i[t] = (Xi[t] - Si[t]) * invden;
        }
        __syncthreads();
        // (e) omega1 power sums from Herm(U1) (no store)
        float n1 = 0.0f, d1 = 0.0f;
#pragma unroll
        for (int t = tid; t < 256; t += NT) {
            int m = (L - t) & (L - 1);
            float hr = 0.5f * (U1r[t] + U1r[m]);
            float hi = 0.5f * (U1i[t] - U1i[m]);
            float p = hr * hr + hi * hi;
            n1 += (float)t * (1.0f / 512.0f) * p;
            d1 += p;
        }
        // block reduction of (n0,d0,n1,d1)
        n0 = warpsum(n0); d0 = warpsum(d0);
        n1 = warpsum(n1); d1 = warpsum(d1);
        {
            int w = tid >> 5;
            if ((tid & 31) == 0) {
                red[w] = n0; red[4 + w] = d0; red[8 + w] = n1; red[12 + w] = d1;
            }
        }
        __syncthreads();
        n0 = red[0] + red[1] + red[2] + red[3];
        d0 = red[4] + red[5] + red[6] + red[7];
        n1 = red[8] + red[9] + red[10] + red[11];
        d1 = red[12] + red[13] + red[14] + red[15];
        om0 = n0 / (d0 + 1e-7f);
        om1 = n1 / (d1 + 1e-7f);
        __syncthreads();
        // (f) lam += tau * (x - real(ifft(U0+U1)))
#pragma unroll
        for (int t = tid; t < L; t += NT) {
            Sr[t] = U0r[t] + U1r[t];
            Si[t] = U0i[t] + U1i[t];
        }
        fft512(Sr, Si, Wr, Wi, 1, tid);   // inverse (unscaled)
#pragma unroll
        for (int t = tid; t < L; t += NT)
            lam[t] += 0.001f * (xs[t] - Sr[t] * (1.0f / 512.0f));
        __syncthreads();
    }

    if (tid == 0) {
        g_omega[sig * 2 + 0] = om0;
        g_omega[sig * 2 + 1] = om1;
    }

    // u0 time-domain -> out[NTOT + ...]  (pre-swap placement)
#pragma unroll
    for (int t = tid; t < L; t += NT) { Sr[t] = U0r[t]; Si[t] = U0i[t]; }
    fft512(Sr, Si, Wr, Wi, 1, tid);
    {
        float* o1 = out + NTOT + (size_t)b * 65536 + d;
#pragma unroll
        for (int t = tid; t < L; t += NT)
            o1[(size_t)t * 128] = Sr[t] * (1.0f / 512.0f);
    }
    // u1 time-domain -> out[2*NTOT + ...]
#pragma unroll
    for (int t = tid; t < L; t += NT) { Sr[t] = U1r[t]; Si[t] = U1i[t]; }
    fft512(Sr, Si, Wr, Wi, 1, tid);
    {
        float* o2 = out + 2 * (size_t)NTOT + (size_t)b * 65536 + d;
#pragma unroll
        for (int t = tid; t < L; t += NT)
            o2[(size_t)t * 128] = Sr[t] * (1.0f / 512.0f);
    }
}

// order[b]: argsort over K=2 of mean_d(omega). Stable: swap iff m1 < m0.
__global__ void order_kernel() {
    __shared__ float sm[64];
    int tid = threadIdx.x;
    if (tid < 64) {
        int b = tid >> 1, k = tid & 1;
        float s = 0.0f;
        for (int dd = 0; dd < 128; dd++)
            s += g_omega[((b << 7) + dd) * 2 + k];
        sm[tid] = s;
    }
    __syncthreads();
    if (tid < 32) g_swap[tid] = (sm[2 * tid + 1] < sm[2 * tid]) ? 1 : 0;
}

// zero x_trend; swap period/res segments where needed (one thread per element)
__global__ void finalize_kernel(float* __restrict__ out) {
    int e = blockIdx.x * blockDim.x + threadIdx.x;
    if (e < NTOT) {
        out[e] = 0.0f;
        int b = e >> 16;   // 512*128 = 65536 elems per batch
        if (g_swap[b]) {
            float a = out[NTOT + e];
            float c = out[2 * NTOT + e];
            out[NTOT + e] = c;
            out[2 * NTOT + e] = a;
        }
    }
}

extern "C" void kernel_launch(void* const* d_in, const int* in_sizes, int n_in,
                              void* d_out, int out_size) {
    const float* x = (const float*)d_in[0];
    float* out = (float*)d_out;
    vmd_main<<<NSIG, NT>>>(x, out);
    order_kernel<<<1, 64>>>();
    finalize_kernel<<<(NTOT + 255) / 256, 256>>>(out);
}

// round 2
// speedup vs baseline: 1.6847x; 1.6847x over previous
#include <cuda_runtime.h>

#define L      512
#define NT     128
#define NSIG   4096
#define NTOT   (32*512*128)
// pad every 8 floats: conflict-free Stockham radix-8 stores (9j+p, gcd(9,32)=1)
#define IDX(c) ((c) + ((c) >> 3))

__device__ float g_omega[NSIG * 2];
__device__ int   g_swap[32];

__device__ __forceinline__ float warpsum(float v) {
#pragma unroll
    for (int o = 16; o; o >>= 1) v += __shfl_xor_sync(0xffffffffu, v, o);
    return v;
}

struct C2 { float x, y; };
__device__ __forceinline__ C2 cadd(C2 a, C2 b) { return {a.x + b.x, a.y + b.y}; }
__device__ __forceinline__ C2 csub(C2 a, C2 b) { return {a.x - b.x, a.y - b.y}; }
__device__ __forceinline__ C2 cmul(C2 a, C2 b) {
    return {a.x * b.x - a.y * b.y, a.x * b.y + a.y * b.x};
}
// a * (i*sgn)
__device__ __forceinline__ C2 cmuli(C2 a, float sgn) { return {-sgn * a.y, sgn * a.x}; }

// 512-pt Stockham radix-8 FFT, 3 stages, natural-order output.
// sgn = -1: forward (e^{-i}); sgn = +1: inverse twiddles. NO 1/N scaling.
// Input in (Ar,Ai), output lands in (Br,Bi). Both clobbered.
// First action is __syncthreads() (covers caller's writes to A).
__device__ void fft512(float* Ar, float* Ai, float* Br, float* Bi,
                       float sgn, int tid) {
    const float S2 = 0.70710678118654752f;
    float *xr = Ar, *xi = Ai, *yr = Br, *yi = Bi;
    int l = 64, m = 1;
    __syncthreads();
#pragma unroll
    for (int st = 0; st < 3; st++) {
        if (tid < 64) {
            int j, k;
            if (st == 0)      { j = tid;      k = 0;       }
            else if (st == 1) { j = tid >> 3; k = tid & 7; }
            else              { j = 0;        k = tid;     }
            C2 c[8];
#pragma unroll
            for (int q = 0; q < 8; q++) {
                int idx = IDX(k + m * (j + l * q));
                c[q].x = xr[idx]; c[q].y = xi[idx];
            }
            // 8-point DFT (DIT), sign-parametrized
            C2 t0 = cadd(c[0], c[4]), t1 = csub(c[0], c[4]);
            C2 t2 = cadd(c[2], c[6]), t3 = cmuli(csub(c[2], c[6]), sgn);
            C2 u0 = cadd(c[1], c[5]), u1 = csub(c[1], c[5]);
            C2 u2 = cadd(c[3], c[7]), u3 = cmuli(csub(c[3], c[7]), sgn);
            C2 E0 = cadd(t0, t2), E2 = csub(t0, t2);
            C2 E1 = cadd(t1, t3), E3 = csub(t1, t3);
            C2 O0 = cadd(u0, u2), O2 = csub(u0, u2);
            C2 O1 = cadd(u1, u3), O3 = csub(u1, u3);
            C2 w1c = { S2, sgn * S2};
            C2 w3c = {-S2, sgn * S2};
            C2 o1 = cmul(O1, w1c);
            C2 o2 = cmuli(O2, sgn);
            C2 o3 = cmul(O3, w3c);
            C2 dd[8];
            dd[0] = cadd(E0, O0); dd[4] = csub(E0, O0);
            dd[1] = cadd(E1, o1); dd[5] = csub(E1, o1);
            dd[2] = cadd(E2, o2); dd[6] = csub(E2, o2);
            dd[3] = cadd(E3, o3); dd[7] = csub(E3, o3);
            if (j) {
                float ang = sgn * 6.283185307179586f * (float)j / (float)(8 * l);
                C2 w, wp;
                __sincosf(ang, &wp.y, &wp.x);
                w = wp;
#pragma unroll
                for (int p = 1; p < 8; p++) {
                    dd[p] = cmul(dd[p], w);
                    w = cmul(w, wp);
                }
            }
#pragma unroll
            for (int p = 0; p < 8; p++) {
                int idx = IDX(k + m * (8 * j + p));
                yr[idx] = dd[p].x; yi[idx] = dd[p].y;
            }
        }
        __syncthreads();
        float* tr = xr; xr = yr; yr = tr;
        float* ti = xi; xi = yi; yi = ti;
        l >>= 3; m <<= 3;
    }
}

// One CTA = one (b,d) signal. Spectra in UNSHIFTED fft order, padded layout.
// shifted bin j <-> unshifted k via k = j ^ 256; f_k = (k<256 ? k : k-512)/512
__global__ void __launch_bounds__(NT) vmd_main(const float* __restrict__ x,
                                               float* __restrict__ out) {
    __shared__ float Xr[576], Xi[576];
    __shared__ float U0r[576], U0i[576], U1r[576], U1i[576];
    __shared__ float Ar[576], Ai[576], Br_[576], Bi_[576];
    __shared__ float lam[576], xs[576];
    __shared__ float red[16];

    const int tid = threadIdx.x;
    const int sig = blockIdx.x;
    const int b = sig >> 7, d = sig & 127;
    const float* xp = x + (size_t)b * 65536 + d;

    // load + init
#pragma unroll
    for (int t = tid; t < L; t += NT) {
        float v = xp[(size_t)t * 128];
        int it = IDX(t);
        xs[it] = v;
        Ar[it] = v;  Ai[it] = 0.0f;
        U1r[it] = 0.0f; U1i[it] = 0.0f;
        lam[it] = 0.0f;
    }
    fft512(Ar, Ai, Br_, Bi_, -1.0f, tid);   // X = fft(x)
#pragma unroll
    for (int t = tid; t < L; t += NT) {
        int it = IDX(t);
        Xr[it] = Br_[it]; Xi[it] = Bi_[it];
    }
    __syncthreads();

    float om0 = 0.0f, om1 = 0.0f;

    for (int iter = 0; iter < 50; iter++) {
        // A: U0 = (X - Herm(U1) + lam'/2) / (1 + 2a(f-om0)^2)
#pragma unroll
        for (int t = tid; t < L; t += NT) {
            int mi = (L - t) & (L - 1);
            int it = IDX(t), im = IDX(mi), il = IDX(t ^ 256);
            float hr = 0.5f * (U1r[it] + U1r[im]);
            float hi = 0.5f * (U1i[it] - U1i[im]);
            float fk = (float)((t < 256) ? t : t - 512) * (1.0f / 512.0f);
            float df = fk - om0;
            float invd = 1.0f / (1.0f + 1600.0f * df * df);
            U0r[it] = (Xr[it] - hr + 0.5f * lam[il]) * invd;
            U0i[it] = (Xi[it] - hi) * invd;
        }
        __syncthreads();
        // B: h = Herm(U0); omega0 sums (t<256); U1 = (X - h + lam'/2)*invd(om1)
        float n0 = 0.0f, d0 = 0.0f;
#pragma unroll
        for (int t = tid; t < L; t += NT) {
            int mi = (L - t) & (L - 1);
            int it = IDX(t), im = IDX(mi), il = IDX(t ^ 256);
            float hr = 0.5f * (U0r[it] + U0r[im]);
            float hi = 0.5f * (U0i[it] - U0i[im]);
            if (t < 256) {
                float p = hr * hr + hi * hi;
                n0 += (float)t * (1.0f / 512.0f) * p;
                d0 += p;
            }
            float fk = (float)((t < 256) ? t : t - 512) * (1.0f / 512.0f);
            float df = fk - om1;
            float invd = 1.0f / (1.0f + 1600.0f * df * df);
            U1r[it] = (Xr[it] - hr + 0.5f * lam[il]) * invd;
            U1i[it] = (Xi[it] - hi) * invd;
        }
        __syncthreads();
        // C: omega1 sums from Herm(U1); build V = U0+U1 into A (FFT input)
        float n1 = 0.0f, d1 = 0.0f;
#pragma unroll
        for (int t = tid; t < L; t += NT) {
            int it = IDX(t);
            if (t < 256) {
                int mi = (L - t) & (L - 1);
                int im = IDX(mi);
                float hr = 0.5f * (U1r[it] + U1r[im]);
                float hi = 0.5f * (U1i[it] - U1i[im]);
                float p = hr * hr + hi * hi;
                n1 += (float)t * (1.0f / 512.0f) * p;
                d1 += p;
            }
            Ar[it] = U0r[it] + U1r[it];
            Ai[it] = U0i[it] + U1i[it];
        }
        // reduce: write partials before fft's entry sync, read after
        n0 = warpsum(n0); d0 = warpsum(d0);
        n1 = warpsum(n1); d1 = warpsum(d1);
        {
            int w = tid >> 5;
            if ((tid & 31) == 0) {
                red[w] = n0; red[4 + w] = d0; red[8 + w] = n1; red[12 + w] = d1;
            }
        }
        fft512(Ar, Ai, Br_, Bi_, +1.0f, tid);   // inverse (unscaled) of U0+U1
        om0 = (red[0] + red[1] + red[2] + red[3]) /
              (red[4] + red[5] + red[6] + red[7] + 1e-7f);
        om1 = (red[8] + red[9] + red[10] + red[11]) /
              (red[12] + red[13] + red[14] + red[15] + 1e-7f);
        // lam += tau * (x - real(ifft(U0+U1)))
#pragma unroll
        for (int t = tid; t < L; t += NT) {
            int it = IDX(t);
            lam[it] += 0.001f * (xs[it] - Br_[it] * (1.0f / 512.0f));
        }
        __syncthreads();
    }

    if (tid == 0) {
        g_omega[sig * 2 + 0] = om0;
        g_omega[sig * 2 + 1] = om1;
    }

    // u0 time-domain -> out[NTOT + ...]
#pragma unroll
    for (int t = tid; t < L; t += NT) {
        int it = IDX(t);
        Ar[it] = U0r[it]; Ai[it] = U0i[it];
    }
    fft512(Ar, Ai, Br_, Bi_, +1.0f, tid);
    {
        float* o1 = out + NTOT + (size_t)b * 65536 + d;
#pragma unroll
        for (int t = tid; t < L; t += NT)
            o1[(size_t)t * 128] = Br_[IDX(t)] * (1.0f / 512.0f);
    }
    // u1 time-domain -> out[2*NTOT + ...]
#pragma unroll
    for (int t = tid; t < L; t += NT) {
        int it = IDX(t);
        Ar[it] = U1r[it]; Ai[it] = U1i[it];
    }
    fft512(Ar, Ai, Br_, Bi_, +1.0f, tid);
    {
        float* o2 = out + 2 * (size_t)NTOT + (size_t)b * 65536 + d;
#pragma unroll
        for (int t = tid; t < L; t += NT)
            o2[(size_t)t * 128] = Br_[IDX(t)] * (1.0f / 512.0f);
    }
}

// order[b]: argsort over K=2 of mean_d(omega). Stable: swap iff m1 < m0.
__global__ void order_kernel() {
    __shared__ float sm[64];
    int tid = threadIdx.x;
    if (tid < 64) {
        int b = tid >> 1, k = tid & 1;
        float s = 0.0f;
        for (int dd = 0; dd < 128; dd++)
            s += g_omega[((b << 7) + dd) * 2 + k];
        sm[tid] = s;
    }
    __syncthreads();
    if (tid < 32) g_swap[tid] = (sm[2 * tid + 1] < sm[2 * tid]) ? 1 : 0;
}

// zero x_trend; swap period/res segments where needed
__global__ void finalize_kernel(float* __restrict__ out) {
    int e = blockIdx.x * blockDim.x + threadIdx.x;
    if (e < NTOT) {
        out[e] = 0.0f;
        int b = e >> 16;
        if (g_swap[b]) {
            float a = out[NTOT + e];
            float c = out[2 * NTOT + e];
            out[NTOT + e] = c;
            out[2 * NTOT + e] = a;
        }
    }
}

extern "C" void kernel_launch(void* const* d_in, const int* in_sizes, int n_in,
                              void* d_out, int out_size) {
    const float* x = (const float*)d_in[0];
    float* out = (float*)d_out;
    vmd_main<<<NSIG, NT>>>(x, out);
    order_kernel<<<1, 64>>>();
    finalize_kernel<<<(NTOT + 255) / 256, 256>>>(out);
}

// round 3
// speedup vs baseline: 2.9922x; 1.7761x over previous
#include <cuda_runtime.h>

#define L      512
#define NT     128
#define NSIG   4096
#define NTOT   (32*512*128)
// pad every 8 floats: conflict-free Stockham radix-8 stores (9j+p, gcd(9,32)=1)
#define IDX(c) ((c) + ((c) >> 3))

__device__ float g_omega[NSIG * 2];
__device__ int   g_swap[32];

__device__ __forceinline__ float warpsum(float v) {
#pragma unroll
    for (int o = 16; o; o >>= 1) v += __shfl_xor_sync(0xffffffffu, v, o);
    return v;
}

struct C2 { float x, y; };
__device__ __forceinline__ C2 cadd(C2 a, C2 b) { return {a.x + b.x, a.y + b.y}; }
__device__ __forceinline__ C2 csub(C2 a, C2 b) { return {a.x - b.x, a.y - b.y}; }
__device__ __forceinline__ C2 cmul(C2 a, C2 b) {
    return {a.x * b.x - a.y * b.y, a.x * b.y + a.y * b.x};
}
__device__ __forceinline__ C2 cmuli(C2 a, float sgn) { return {-sgn * a.y, sgn * a.x}; }

// 512-pt Stockham radix-8 FFT, 3 stages, natural-order output.
// sgn=-1 forward, sgn=+1 inverse twiddles. NO 1/N scaling.
// Input (Ar,Ai) -> output (Br,Bi). First action is __syncthreads().
__device__ void fft512(float* Ar, float* Ai, float* Br, float* Bi,
                       float sgn, int tid) {
    const float S2 = 0.70710678118654752f;
    float *xr = Ar, *xi = Ai, *yr = Br, *yi = Bi;
    int l = 64, m = 1;
    __syncthreads();
#pragma unroll
    for (int st = 0; st < 3; st++) {
        if (tid < 64) {
            int j, k;
            if (st == 0)      { j = tid;      k = 0;       }
            else if (st == 1) { j = tid >> 3; k = tid & 7; }
            else              { j = 0;        k = tid;     }
            C2 c[8];
#pragma unroll
            for (int q = 0; q < 8; q++) {
                int idx = IDX(k + m * (j + l * q));
                c[q].x = xr[idx]; c[q].y = xi[idx];
            }
            C2 t0 = cadd(c[0], c[4]), t1 = csub(c[0], c[4]);
            C2 t2 = cadd(c[2], c[6]), t3 = cmuli(csub(c[2], c[6]), sgn);
            C2 u0 = cadd(c[1], c[5]), u1 = csub(c[1], c[5]);
            C2 u2 = cadd(c[3], c[7]), u3 = cmuli(csub(c[3], c[7]), sgn);
            C2 E0 = cadd(t0, t2), E2 = csub(t0, t2);
            C2 E1 = cadd(t1, t3), E3 = csub(t1, t3);
            C2 O0 = cadd(u0, u2), O2 = csub(u0, u2);
            C2 O1 = cadd(u1, u3), O3 = csub(u1, u3);
            C2 w1c = { S2, sgn * S2};
            C2 w3c = {-S2, sgn * S2};
            C2 o1 = cmul(O1, w1c);
            C2 o2 = cmuli(O2, sgn);
            C2 o3 = cmul(O3, w3c);
            C2 dd[8];
            dd[0] = cadd(E0, O0); dd[4] = csub(E0, O0);
            dd[1] = cadd(E1, o1); dd[5] = csub(E1, o1);
            dd[2] = cadd(E2, o2); dd[6] = csub(E2, o2);
            dd[3] = cadd(E3, o3); dd[7] = csub(E3, o3);
            if (j) {
                float ang = sgn * 6.283185307179586f * (float)j / (float)(8 * l);
                C2 w, wp;
                __sincosf(ang, &wp.y, &wp.x);
                w = wp;
#pragma unroll
                for (int p = 1; p < 8; p++) {
                    dd[p] = cmul(dd[p], w);
                    w = cmul(w, wp);
                }
            }
#pragma unroll
            for (int p = 0; p < 8; p++) {
                int idx = IDX(k + m * (8 * j + p));
                yr[idx] = dd[p].x; yi[idx] = dd[p].y;
            }
        }
        __syncthreads();
        float* tr = xr; xr = yr; yr = tr;
        float* ti = xi; xi = yi; yi = ti;
        l >>= 3; m <<= 3;
    }
}

// One CTA = one (b,d) signal. All spectra register-resident.
// Thread i>=1 owns bins {i, 256-i, 256+i, 512-i}; thread 0 owns {0,128,256,384}.
// Mirror (512-t)&511: slots (0<->3, 1<->2) general, (0<->0, 1<->3, 2<->2) for t0.
// Xor-256 (lambda shift): slots (0<->2, 1<->3) for everyone.
__global__ void __launch_bounds__(NT, 6) vmd_main(const float* __restrict__ x,
                                                  float* __restrict__ out) {
    __shared__ float Ar[576], Ai[576], Br_[576], Bi_[576];
    __shared__ float red[32];

    const int tid = threadIdx.x;
    const int sig = blockIdx.x;
    const int b = sig >> 7, d = sig & 127;
    const float* xp = x + (size_t)b * 65536 + d;

    const bool isT0 = (tid == 0);
    const int tv0 = isT0 ? 0   : tid;
    const int tv1 = isT0 ? 128 : 256 - tid;
    const int tv2 = isT0 ? 256 : 256 + tid;
    const int tv3 = isT0 ? 384 : 512 - tid;
    const int i0 = IDX(tv0), i1 = IDX(tv1), i2 = IDX(tv2), i3 = IDX(tv3);
    const float f0 = (float)tv0 * (1.0f / 512.0f);            // >= 0
    const float f1 = (float)tv1 * (1.0f / 512.0f);            // >= 0
    const float f2 = (float)(tv2 - 512) * (1.0f / 512.0f);    // < 0
    const float f3 = (float)(tv3 - 512) * (1.0f / 512.0f);    // <= 0

    const float xs0 = xp[(size_t)tv0 * 128];
    const float xs1 = xp[(size_t)tv1 * 128];
    const float xs2 = xp[(size_t)tv2 * 128];
    const float xs3 = xp[(size_t)tv3 * 128];

    // forward FFT of x
    Ar[i0] = xs0; Ai[i0] = 0.0f;
    Ar[i1] = xs1; Ai[i1] = 0.0f;
    Ar[i2] = xs2; Ai[i2] = 0.0f;
    Ar[i3] = xs3; Ai[i3] = 0.0f;
    fft512(Ar, Ai, Br_, Bi_, -1.0f, tid);
    const float X0r = Br_[i0], X0i = Bi_[i0];
    const float X1r = Br_[i1], X1i = Bi_[i1];
    const float X2r = Br_[i2], X2i = Bi_[i2];
    const float X3r = Br_[i3], X3i = Bi_[i3];

    float u0r0, u0i0, u0r1, u0i1, u0r2, u0i2, u0r3, u0i3;
    float u1r0 = 0.f, u1i0 = 0.f, u1r1 = 0.f, u1i1 = 0.f;
    float u1r2 = 0.f, u1i2 = 0.f, u1r3 = 0.f, u1i3 = 0.f;
    float l0 = 0.f, l1 = 0.f, l2 = 0.f, l3 = 0.f;
    float om0 = 0.0f, om1 = 0.0f;

    for (int iter = 0; iter < 50; iter++) {
        // ---- Pass A: U0 = (X - Herm(U1) + lam'/2) / (1 + 2a(f-om0)^2)
        float m0r = isT0 ? u1r0 : u1r3, m0i = isT0 ? u1i0 : u1i3;
        float m1r = isT0 ? u1r3 : u1r2, m1i = isT0 ? u1i3 : u1i2;
        float m2r = isT0 ? u1r2 : u1r1, m2i = isT0 ? u1i2 : u1i1;
        float m3r = isT0 ? u1r1 : u1r0, m3i = isT0 ? u1i1 : u1i0;
        float h0r = 0.5f * (u1r0 + m0r), h0i = 0.5f * (u1i0 - m0i);
        float h1r = 0.5f * (u1r1 + m1r), h1i = 0.5f * (u1i1 - m1i);
        float h2r = 0.5f * (u1r2 + m2r), h2i = 0.5f * (u1i2 - m2i);
        float h3r = 0.5f * (u1r3 + m3r), h3i = 0.5f * (u1i3 - m3i);
        float df, q;
        df = f0 - om0; q = __frcp_rn(fmaf(1600.0f * df, df, 1.0f));
        u0r0 = (X0r - h0r + 0.5f * l2) * q; u0i0 = (X0i - h0i) * q;
        df = f1 - om0; q = __frcp_rn(fmaf(1600.0f * df, df, 1.0f));
        u0r1 = (X1r - h1r + 0.5f * l3) * q; u0i1 = (X1i - h1i) * q;
        df = f2 - om0; q = __frcp_rn(fmaf(1600.0f * df, df, 1.0f));
        u0r2 = (X2r - h2r + 0.5f * l0) * q; u0i2 = (X2i - h2i) * q;
        df = f3 - om0; q = __frcp_rn(fmaf(1600.0f * df, df, 1.0f));
        u0r3 = (X3r - h3r + 0.5f * l1) * q; u0i3 = (X3i - h3i) * q;

        // ---- Pass B: h = Herm(U0); omega0 sums (f>=0 slots 0,1); U1 update
        m0r = isT0 ? u0r0 : u0r3; m0i = isT0 ? u0i0 : u0i3;
        m1r = isT0 ? u0r3 : u0r2; m1i = isT0 ? u0i3 : u0i2;
        m2r = isT0 ? u0r2 : u0r1; m2i = isT0 ? u0i2 : u0i1;
        m3r = isT0 ? u0r1 : u0r0; m3i = isT0 ? u0i1 : u0i0;
        h0r = 0.5f * (u0r0 + m0r); h0i = 0.5f * (u0i0 - m0i);
        h1r = 0.5f * (u0r1 + m1r); h1i = 0.5f * (u0i1 - m1i);
        h2r = 0.5f * (u0r2 + m2r); h2i = 0.5f * (u0i2 - m2i);
        h3r = 0.5f * (u0r3 + m3r); h3i = 0.5f * (u0i3 - m3i);
        float p0 = h0r * h0r + h0i * h0i;
        float p1 = h1r * h1r + h1i * h1i;
        float n0 = f0 * p0 + f1 * p1, den0 = p0 + p1;
        df = f0 - om1; q = __frcp_rn(fmaf(1600.0f * df, df, 1.0f));
        u1r0 = (X0r - h0r + 0.5f * l2) * q; u1i0 = (X0i - h0i) * q;
        df = f1 - om1; q = __frcp_rn(fmaf(1600.0f * df, df, 1.0f));
        u1r1 = (X1r - h1r + 0.5f * l3) * q; u1i1 = (X1i - h1i) * q;
        df = f2 - om1; q = __frcp_rn(fmaf(1600.0f * df, df, 1.0f));
        u1r2 = (X2r - h2r + 0.5f * l0) * q; u1i2 = (X2i - h2i) * q;
        df = f3 - om1; q = __frcp_rn(fmaf(1600.0f * df, df, 1.0f));
        u1r3 = (X3r - h3r + 0.5f * l1) * q; u1i3 = (X3i - h3i) * q;

        // ---- Pass C: omega1 sums from Herm(U1); scatter V = U0+U1
        m0r = isT0 ? u1r0 : u1r3; m0i = isT0 ? u1i0 : u1i3;
        m1r = isT0 ? u1r3 : u1r2; m1i = isT0 ? u1i3 : u1i2;
        h0r = 0.5f * (u1r0 + m0r); h0i = 0.5f * (u1i0 - m0i);
        h1r = 0.5f * (u1r1 + m1r); h1i = 0.5f * (u1i1 - m1i);
        p0 = h0r * h0r + h0i * h0i;
        p1 = h1r * h1r + h1i * h1i;
        float n1 = f0 * p0 + f1 * p1, den1 = p0 + p1;

        Ar[i0] = u0r0 + u1r0; Ai[i0] = u0i0 + u1i0;
        Ar[i1] = u0r1 + u1r1; Ai[i1] = u0i1 + u1i1;
        Ar[i2] = u0r2 + u1r2; Ai[i2] = u0i2 + u1i2;
        Ar[i3] = u0r3 + u1r3; Ai[i3] = u0i3 + u1i3;

        // block reduction, parity double-buffered (no extra barrier needed)
        n0 = warpsum(n0); den0 = warpsum(den0);
        n1 = warpsum(n1); den1 = warpsum(den1);
        {
            int po = (iter & 1) << 4;
            int w = tid >> 5;
            if ((tid & 31) == 0) {
                red[po + w] = n0;      red[po + 4 + w] = den0;
                red[po + 8 + w] = n1;  red[po + 12 + w] = den1;
            }
        }
        fft512(Ar, Ai, Br_, Bi_, +1.0f, tid);   // inverse (unscaled) of U0+U1
        {
            int po = (iter & 1) << 4;
            om0 = (red[po + 0] + red[po + 1] + red[po + 2] + red[po + 3]) /
                  (red[po + 4] + red[po + 5] + red[po + 6] + red[po + 7] + 1e-7f);
            om1 = (red[po + 8] + red[po + 9] + red[po + 10] + red[po + 11]) /
                  (red[po + 12] + red[po + 13] + red[po + 14] + red[po + 15] + 1e-7f);
        }
        // lam += tau * (x - real(ifft(U0+U1))/512)
        l0 = fmaf(0.001f, xs0 - Br_[i0] * (1.0f / 512.0f), l0);
        l1 = fmaf(0.001f, xs1 - Br_[i1] * (1.0f / 512.0f), l1);
        l2 = fmaf(0.001f, xs2 - Br_[i2] * (1.0f / 512.0f), l2);
        l3 = fmaf(0.001f, xs3 - Br_[i3] * (1.0f / 512.0f), l3);
    }

    if (tid == 0) {
        g_omega[sig * 2 + 0] = om0;
        g_omega[sig * 2 + 1] = om1;
    }

    // u0 time-domain -> out[NTOT + ...]
    Ar[i0] = u0r0; Ai[i0] = u0i0;
    Ar[i1] = u0r1; Ai[i1] = u0i1;
    Ar[i2] = u0r2; Ai[i2] = u0i2;
    Ar[i3] = u0r3; Ai[i3] = u0i3;
    fft512(Ar, Ai, Br_, Bi_, +1.0f, tid);
    {
        float* o1 = out + NTOT + (size_t)b * 65536 + d;
        o1[(size_t)tv0 * 128] = Br_[i0] * (1.0f / 512.0f);
        o1[(size_t)tv1 * 128] = Br_[i1] * (1.0f / 512.0f);
        o1[(size_t)tv2 * 128] = Br_[i2] * (1.0f / 512.0f);
        o1[(size_t)tv3 * 128] = Br_[i3] * (1.0f / 512.0f);
    }
    // u1 time-domain -> out[2*NTOT + ...]
    Ar[i0] = u1r0; Ai[i0] = u1i0;
    Ar[i1] = u1r1; Ai[i1] = u1i1;
    Ar[i2] = u1r2; Ai[i2] = u1i2;
    Ar[i3] = u1r3; Ai[i3] = u1i3;
    fft512(Ar, Ai, Br_, Bi_, +1.0f, tid);
    {
        float* o2 = out + 2 * (size_t)NTOT + (size_t)b * 65536 + d;
        o2[(size_t)tv0 * 128] = Br_[i0] * (1.0f / 512.0f);
        o2[(size_t)tv1 * 128] = Br_[i1] * (1.0f / 512.0f);
        o2[(size_t)tv2 * 128] = Br_[i2] * (1.0f / 512.0f);
        o2[(size_t)tv3 * 128] = Br_[i3] * (1.0f / 512.0f);
    }
}

// order[b]: argsort over K=2 of mean_d(omega). Stable: swap iff m1 < m0.
__global__ void order_kernel() {
    __shared__ float sm[64];
    int tid = threadIdx.x;
    if (tid < 64) {
        int b = tid >> 1, k = tid & 1;
        float s = 0.0f;
        for (int dd = 0; dd < 128; dd++)
            s += g_omega[((b << 7) + dd) * 2 + k];
        sm[tid] = s;
    }
    __syncthreads();
    if (tid < 32) g_swap[tid] = (sm[2 * tid + 1] < sm[2 * tid]) ? 1 : 0;
}

// zero x_trend; swap period/res segments where needed
__global__ void finalize_kernel(float* __restrict__ out) {
    int e = blockIdx.x * blockDim.x + threadIdx.x;
    if (e < NTOT) {
        out[e] = 0.0f;
        int b = e >> 16;
        if (g_swap[b]) {
            float a = out[NTOT + e];
            float c = out[2 * NTOT + e];
            out[NTOT + e] = c;
            out[2 * NTOT + e] = a;
        }
    }
}

extern "C" void kernel_launch(void* const* d_in, const int* in_sizes, int n_in,
                              void* d_out, int out_size) {
    const float* x = (const float*)d_in[0];
    float* out = (float*)d_out;
    vmd_main<<<NSIG, NT>>>(x, out);
    order_kernel<<<1, 64>>>();
    finalize_kernel<<<(NTOT + 255) / 256, 256>>>(out);
}